// round 9
// baseline (speedup 1.0000x reference)
#include <cuda_runtime.h>

#define HEIGHT  260
#define WIDTH   346
#define H_S     65
#define W_S     86
#define T_STEPS 64
#define BATCH   16
#define IMG     (H_S * W_S)      // 5590

// scratch: exc for all (t,b) — 22.9 MB, L2-resident
__device__ float g_exc[T_STEPS * BATCH * IMG];

// ---------------------------------------------------------------------------
// Kernel A (locked-in best config: 127 µs, DRAM 75%, occ 90%):
// 4x4 avg pool (2 ch) + 2-ch 3x3 conv + ReLU -> g_exc.
// ---------------------------------------------------------------------------
__global__ void __launch_bounds__(512)
k_exc(const float* __restrict__ x, const float* __restrict__ exc_w,
      float* __restrict__ out_dcmd) {
    const int tb = blockIdx.x;                       // t*BATCH + b
    const float* xb = x + (long long)tb * 2 * HEIGHT * WIDTH;

    __shared__ float p[2][67][88];                   // pooled + 1-halo
    __shared__ float w[18];

    const int tid = threadIdx.x;
    if (tid < 18) w[tid] = exc_w[tid];
    if (tid == 511) out_dcmd[tb] = 0.f;              // zero-init dcmd (poisoned)

    for (int n = tid; n < 2 * 88; n += 512) {
        int c = n / 88, j = n % 88;
        p[c][0][j] = 0.f;  p[c][H_S + 1][j] = 0.f;
    }
    for (int n = tid; n < 2 * 67; n += 512) {
        int c = n / 67, i = n % 67;
        p[c][i][0] = 0.f;  p[c][i][W_S + 1] = 0.f;
    }
    __syncthreads();

    for (int n = tid; n < 2 * IMG; n += 512) {
        int c   = n / IMG;
        int rem = n - c * IMG;
        int i   = rem / W_S;
        int j   = rem - i * W_S;
        const float* src = xb + ((long long)c * HEIGHT + i * 4) * WIDTH + j * 4;
        float4 a  = *(const float4*)(src);
        float2 b0 = *(const float2*)(src + WIDTH);
        float2 b1 = *(const float2*)(src + WIDTH + 2);
        float4 c4 = *(const float4*)(src + 2 * WIDTH);
        float2 d0 = *(const float2*)(src + 3 * WIDTH);
        float2 d1 = *(const float2*)(src + 3 * WIDTH + 2);
        float s = a.x + a.y + a.z + a.w
                + b0.x + b0.y + b1.x + b1.y
                + c4.x + c4.y + c4.z + c4.w
                + d0.x + d0.y + d1.x + d1.y;
        p[c][i + 1][j + 1] = s * (1.f / 16.f);
    }
    __syncthreads();

    float* out = g_exc + (long long)tb * IMG;
    for (int n = tid; n < IMG; n += 512) {
        int i = n / W_S;
        int j = n - i * W_S;
        float acc = 0.f;
        #pragma unroll
        for (int c = 0; c < 2; c++)
            #pragma unroll
            for (int ky = 0; ky < 3; ky++)
                #pragma unroll
                for (int kx = 0; kx < 3; kx++)
                    acc += p[c][i + ky][j + kx] * w[c * 9 + ky * 3 + kx];
        out[n] = fmaxf(acc, 0.f);
    }
}

// ---------------------------------------------------------------------------
// Kernel B: fused separable-conv + membrane scan + dcmd.
// Block = (batch b, 8-row strip). 144 blocks (one wave), 704 threads.
// Per step t: stage exc[t-1] (14x92, 3-halo) -> h-pass -> v-pass + membrane
// (v in register) + spike store + per-warp RED dcmd. exc[t] prefetched.
// Single rp buffer: v-pass(t) / h-pass(t+1) are ordered by the stage barrier.
// ---------------------------------------------------------------------------
#define RG     8                      // rows per strip
#define NG     9                      // 9*8 = 72 >= 65
#define BUFR   (RG + 6)               // 14
#define RAWW   (W_S + 6)              // 92
#define RPW    88
#define NT3    704                    // 22 warps; 8*86 = 688 active px

__global__ void __launch_bounds__(NT3)
k_vscan(const float* __restrict__ inh_w, const float* __restrict__ dcmd_w,
        float* __restrict__ out_dcmd, float* __restrict__ out_spk) {
    const int b     = blockIdx.x;
    const int g     = blockIdx.y;
    const int row0  = g * RG;
    const int nrows = min(RG, H_S - row0);
    const int tid   = threadIdx.x;

    __shared__ float raw[BUFR][RAWW];
    __shared__ float rp [BUFR][RPW];

    float u[7];
    {
        float cnorm = rsqrtf(-__ldg(&inh_w[3 * 7 + 3]));
        #pragma unroll
        for (int j = 0; j < 7; j++) u[j] = -__ldg(&inh_w[3 * 7 + j]) * cnorm;
    }

    const int npx = nrows * W_S;                 // active pixels this strip
    const bool act = tid < npx;
    const int r = tid / W_S;                     // row within strip
    const int c = tid - r * W_S;

    const long long pbase = (long long)row0 * W_S + tid;   // offset within image
    const float adw = act ? fabsf(__ldg(&dcmd_w[pbase])) : 0.f;

    const int stage_elems = (nrows + 6) * RAWW;
    const int hp_elems    = (nrows + 6) * W_S;

    float v = 0.f;
    float e_cur = act ? __ldg(&g_exc[(long long)b * IMG + pbase]) : 0.f;

    for (int t = 0; t < T_STEPS; t++) {
        // prefetch exc[t+1] (consumed next iteration, hidden behind barriers)
        float e_next = 0.f;
        if (t + 1 < T_STEPS && act)
            e_next = __ldg(&g_exc[((long long)(t + 1) * BATCH + b) * IMG + pbase]);

        float inh = 0.f;
        if (t > 0) {
            // stage exc[t-1] strip with 3-halo (zero outside)
            const float* prev = g_exc + ((long long)(t - 1) * BATCH + b) * IMG;
            for (int n = tid; n < stage_elems; n += NT3) {
                int rr = n / RAWW;
                int cc = n - rr * RAWW;
                int gr = row0 - 3 + rr;
                int gc = cc - 3;
                float val = 0.f;
                if (gr >= 0 && gr < H_S && gc >= 0 && gc < W_S)
                    val = __ldg(&prev[gr * W_S + gc]);
                raw[rr][cc] = val;
            }
            __syncthreads();                     // stage barrier

            // horizontal 7-tap
            for (int n = tid; n < hp_elems; n += NT3) {
                int rr = n / W_S;
                int cc = n - rr * W_S;
                float acc = 0.f;
                #pragma unroll
                for (int k = 0; k < 7; k++) acc += raw[rr][cc + k] * u[k];
                rp[rr][cc] = acc;
            }
            __syncthreads();                     // h-pass barrier

            // vertical 7-tap (inhibition, negative of conv result)
            if (act) {
                #pragma unroll
                for (int k = 0; k < 7; k++) inh += rp[r + k][c] * u[k];
            }
        }

        // membrane update + spike + dcmd
        float dsum = 0.f;
        if (act) {
            float lg = e_cur - inh;
            float vn = v + (lg - v) * 0.5f;      // tau = 2 exact
            float sp = (vn >= 1.0f) ? 1.0f : 0.0f;
            out_spk[((long long)t * BATCH + b) * IMG + pbase] = sp;
            v = vn * (1.0f - sp);
            dsum = sp * adw;
        }
        e_cur = e_next;

        #pragma unroll
        for (int off = 16; off; off >>= 1)
            dsum += __shfl_down_sync(0xffffffffu, dsum, off);
        if ((tid & 31) == 0 && dsum != 0.f)
            atomicAdd(&out_dcmd[t * BATCH + b], dsum);   // RED, fire-and-forget
    }
}

extern "C" void kernel_launch(void* const* d_in, const int* in_sizes, int n_in,
                              void* d_out, int out_size) {
    const float* x      = (const float*)d_in[0];
    const float* exc_w  = (const float*)d_in[1];
    const float* inh_w  = (const float*)d_in[2];
    const float* dcmd_w = (const float*)d_in[3];

    float* out      = (float*)d_out;
    float* out_dcmd = out;                         // (T,B)
    float* out_spk  = out + T_STEPS * BATCH;       // (T,B,1,H_S,W_S)

    k_exc<<<T_STEPS * BATCH, 512>>>(x, exc_w, out_dcmd);
    dim3 gv(BATCH, NG);
    k_vscan<<<gv, NT3>>>(inh_w, dcmd_w, out_dcmd, out_spk);
}

// round 10
// speedup vs baseline: 1.2254x; 1.2254x over previous
#include <cuda_runtime.h>

#define HEIGHT  260
#define WIDTH   346
#define H_S     65
#define W_S     86
#define T_STEPS 64
#define BATCH   16
#define IMG     (H_S * W_S)      // 5590

// scratch (L2-resident)
__device__ float g_exc [T_STEPS * BATCH * IMG];
__device__ float g_lgmd[T_STEPS * BATCH * IMG];

// ---------------------------------------------------------------------------
// Kernel A (locked: 127 µs, DRAM 75%, occ 90%): pool + 3x3 conv + ReLU.
// t=0 blocks also seed g_lgmd (lgmd_in[0] = exc[0]).
// ---------------------------------------------------------------------------
__global__ void __launch_bounds__(512)
k_exc(const float* __restrict__ x, const float* __restrict__ exc_w,
      float* __restrict__ out_dcmd) {
    const int tb = blockIdx.x;                       // t*BATCH + b
    const float* xb = x + (long long)tb * 2 * HEIGHT * WIDTH;

    __shared__ float p[2][67][88];                   // pooled + 1-halo
    __shared__ float w[18];

    const int tid = threadIdx.x;
    if (tid < 18) w[tid] = exc_w[tid];
    if (tid == 511) out_dcmd[tb] = 0.f;              // zero-init dcmd (poisoned)

    for (int n = tid; n < 2 * 88; n += 512) {
        int c = n / 88, j = n % 88;
        p[c][0][j] = 0.f;  p[c][H_S + 1][j] = 0.f;
    }
    for (int n = tid; n < 2 * 67; n += 512) {
        int c = n / 67, i = n % 67;
        p[c][i][0] = 0.f;  p[c][i][W_S + 1] = 0.f;
    }
    __syncthreads();

    for (int n = tid; n < 2 * IMG; n += 512) {
        int c   = n / IMG;
        int rem = n - c * IMG;
        int i   = rem / W_S;
        int j   = rem - i * W_S;
        const float* src = xb + ((long long)c * HEIGHT + i * 4) * WIDTH + j * 4;
        float4 a  = *(const float4*)(src);
        float2 b0 = *(const float2*)(src + WIDTH);
        float2 b1 = *(const float2*)(src + WIDTH + 2);
        float4 c4 = *(const float4*)(src + 2 * WIDTH);
        float2 d0 = *(const float2*)(src + 3 * WIDTH);
        float2 d1 = *(const float2*)(src + 3 * WIDTH + 2);
        float s = a.x + a.y + a.z + a.w
                + b0.x + b0.y + b1.x + b1.y
                + c4.x + c4.y + c4.z + c4.w
                + d0.x + d0.y + d1.x + d1.y;
        p[c][i + 1][j + 1] = s * (1.f / 16.f);
    }
    __syncthreads();

    const bool t0 = (tb < BATCH);
    float* out  = g_exc  + (long long)tb * IMG;
    float* outl = g_lgmd + (long long)tb * IMG;
    for (int n = tid; n < IMG; n += 512) {
        int i = n / W_S;
        int j = n - i * W_S;
        float acc = 0.f;
        #pragma unroll
        for (int c = 0; c < 2; c++)
            #pragma unroll
            for (int ky = 0; ky < 3; ky++)
                #pragma unroll
                for (int kx = 0; kx < 3; kx++)
                    acc += p[c][i + ky][j + kx] * w[c * 9 + ky * 3 + kx];
        acc = fmaxf(acc, 0.f);
        out[n] = acc;
        if (t0) outl[n] = acc;                       // lgmd_in[0] = exc[0]
    }
}

// ---------------------------------------------------------------------------
// Kernel B: lgmd_in[t] = exc[t] - sepconv7x7(exc[t-1]), t >= 1.
// ONE block per (t,b) image: 1008 blocks, 512 threads, smem 51 KB (4 CTA/SM).
// ---------------------------------------------------------------------------
#define IH   (H_S + 6)              // 71
#define IW   (W_S + 6)              // 92
#define W2   43

__global__ void __launch_bounds__(512)
k_inh(const float* __restrict__ inh_w) {
    const int tb  = blockIdx.x + BATCH;              // skip t=0
    const int tid = threadIdx.x;

    __shared__ float raw[IH][IW];
    __shared__ float rp [IH][W_S + 2];

#if defined(__CUDA_ARCH__) && (__CUDACC_VER_MAJOR__ >= 12)
    cudaGridDependencySynchronize();                 // PDL: wait for k_exc writes
#endif

    float u[7];
    {
        float cnorm = rsqrtf(-__ldg(&inh_w[3 * 7 + 3]));
        #pragma unroll
        for (int j = 0; j < 7; j++) u[j] = -__ldg(&inh_w[3 * 7 + j]) * cnorm;
    }

    const float* prev = g_exc + (long long)(tb - BATCH) * IMG;  // exc[t-1]

    // stage exc[t-1] full image with 3-halo (zero outside)
    for (int n = tid; n < IH * IW; n += 512) {
        int r  = n / IW;
        int c  = n - r * IW;
        int gr = r - 3;
        int gc = c - 3;
        float val = 0.f;
        if (gr >= 0 && gr < H_S && gc >= 0 && gc < W_S)
            val = __ldg(&prev[gr * W_S + gc]);
        raw[r][c] = val;
    }
    __syncthreads();

    // horizontal 7-tap
    for (int n = tid; n < IH * W_S; n += 512) {
        int r = n / W_S;
        int c = n - r * W_S;
        float acc = 0.f;
        #pragma unroll
        for (int k = 0; k < 7; k++) acc += raw[r][c + k] * u[k];
        rp[r][c] = acc;
    }
    __syncthreads();

#if defined(__CUDA_ARCH__) && (__CUDACC_VER_MAJOR__ >= 12)
    cudaTriggerProgrammaticLaunchCompletion();       // PDL: let k_scan spin up
#endif

    // vertical 7-tap + subtract from exc[t], float2
    const float2* cur2 = (const float2*)(g_exc + (long long)tb * IMG);
    float2* out2 = (float2*)(g_lgmd + (long long)tb * IMG);
    float2 (*rp2)[W2 + 1] = (float2(*)[W2 + 1])rp;   // 88 floats = 44 float2/row
    for (int n = tid; n < H_S * W2; n += 512) {
        int r = n / W2;
        int c = n - r * W2;
        float cx = 0.f, cy = 0.f;
        #pragma unroll
        for (int k = 0; k < 7; k++) {
            float2 rv = rp2[r + k][c];
            cx += rv.x * u[k];
            cy += rv.y * u[k];
        }
        float2 ev = __ldg(&cur2[n]);
        ev.x -= cx;  ev.y -= cy;
        out2[n] = ev;
    }
}

// ---------------------------------------------------------------------------
// Kernel C: pointwise membrane scan + fused dcmd. 2 px/thread, depth-4
// prefetch ring, barrier-free, one RED per warp per step. unroll 8.
// ---------------------------------------------------------------------------
#define SCT   128
#define IMG2  (IMG / 2)                    // 2795
#define SCB   ((IMG2 + SCT - 1) / SCT)     // 22

__global__ void k_scan(const float* __restrict__ dcmd_w,
                       float* __restrict__ out_dcmd,
                       float* __restrict__ out_spk) {
    const int b   = blockIdx.y;
    const int tid = threadIdx.x;
    const int p2  = blockIdx.x * SCT + tid;
    const bool act = p2 < IMG2;

    const long long base2   = (long long)b * IMG2 + p2;
    const long long stride2 = (long long)BATCH * IMG2;
    const float2* lg2 = (const float2*)g_lgmd;
    float2* out2 = (float2*)out_spk;

    float a0 = 0.f, a1 = 0.f;
    if (act) {
        float2 wv = __ldg(&((const float2*)dcmd_w)[p2]);
        a0 = fabsf(wv.x);  a1 = fabsf(wv.y);
    }

#if defined(__CUDA_ARCH__) && (__CUDACC_VER_MAJOR__ >= 12)
    cudaGridDependencySynchronize();                 // PDL: wait for k_inh
#endif

    float v0 = 0.f, v1 = 0.f;
    float2 ring[4];
    #pragma unroll
    for (int k = 0; k < 4; k++)
        ring[k] = act ? __ldg(&lg2[k * stride2 + base2]) : make_float2(0.f, 0.f);

    #pragma unroll 8
    for (int t = 0; t < T_STEPS; t++) {
        float2 lg = ring[t & 3];
        if (t + 4 < T_STEPS)
            ring[t & 3] = act ? __ldg(&lg2[(t + 4) * stride2 + base2])
                              : make_float2(0.f, 0.f);

        float vn0 = v0 + (lg.x - v0) * 0.5f;         // tau = 2 exact
        float vn1 = v1 + (lg.y - v1) * 0.5f;
        float sp0 = (vn0 >= 1.0f) ? 1.0f : 0.0f;
        float sp1 = (vn1 >= 1.0f) ? 1.0f : 0.0f;
        if (act) out2[t * stride2 + base2] = make_float2(sp0, sp1);
        v0 = vn0 * (1.0f - sp0);
        v1 = vn1 * (1.0f - sp1);

        float dsum = sp0 * a0 + sp1 * a1;
        #pragma unroll
        for (int off = 16; off; off >>= 1)
            dsum += __shfl_down_sync(0xffffffffu, dsum, off);
        if ((tid & 31) == 0 && dsum != 0.f)
            atomicAdd(&out_dcmd[t * BATCH + b], dsum);
    }
}

// helper: launch with PDL if available; fall back to plain launch on error
template <typename... Args>
static void launch_pdl(void (*kern)(Args...), dim3 grid, dim3 block,
                       cudaStream_t stream, Args... args) {
    cudaLaunchAttribute attr[1];
    attr[0].id = cudaLaunchAttributeProgrammaticStreamSerialization;
    attr[0].val.programmaticStreamSerializationAllowed = 1;
    cudaLaunchConfig_t cfg = {};
    cfg.gridDim = grid;  cfg.blockDim = block;
    cfg.dynamicSmemBytes = 0;  cfg.stream = stream;
    cfg.attrs = attr;  cfg.numAttrs = 1;
    cudaError_t err = cudaLaunchKernelEx(&cfg, kern, args...);
    if (err != cudaSuccess) {                        // PDL unsupported: plain
        cudaGetLastError();
        kern<<<grid, block, 0, stream>>>(args...);
    }
}

extern "C" void kernel_launch(void* const* d_in, const int* in_sizes, int n_in,
                              void* d_out, int out_size) {
    const float* x      = (const float*)d_in[0];
    const float* exc_w  = (const float*)d_in[1];
    const float* inh_w  = (const float*)d_in[2];
    const float* dcmd_w = (const float*)d_in[3];

    float* out      = (float*)d_out;
    float* out_dcmd = out;                         // (T,B)
    float* out_spk  = out + T_STEPS * BATCH;       // (T,B,1,H_S,W_S)

    k_exc<<<T_STEPS * BATCH, 512>>>(x, exc_w, out_dcmd);

    launch_pdl(k_inh, dim3((T_STEPS - 1) * BATCH), dim3(512),
               (cudaStream_t)0, inh_w);

    launch_pdl(k_scan, dim3(SCB, BATCH), dim3(SCT),
               (cudaStream_t)0, dcmd_w, out_dcmd, out_spk);
}

// round 11
// speedup vs baseline: 1.2754x; 1.0409x over previous
#include <cuda_runtime.h>

#define HEIGHT  260
#define WIDTH   346
#define H_S     65
#define W_S     86
#define T_STEPS 64
#define BATCH   16
#define IMG     (H_S * W_S)      // 5590

// scratch (L2-resident)
__device__ float g_exc [T_STEPS * BATCH * IMG];
__device__ float g_lgmd[T_STEPS * BATCH * IMG];

// ---------------------------------------------------------------------------
// Kernel A (locked: ~125 µs, DRAM 76%): pool + 3x3 conv + ReLU.
// t=0 blocks also seed g_lgmd (lgmd_in[0] = exc[0]).
// ---------------------------------------------------------------------------
__global__ void __launch_bounds__(512)
k_exc(const float* __restrict__ x, const float* __restrict__ exc_w,
      float* __restrict__ out_dcmd) {
    const int tb = blockIdx.x;                       // t*BATCH + b
    const float* xb = x + (long long)tb * 2 * HEIGHT * WIDTH;

    __shared__ float p[2][67][88];                   // pooled + 1-halo
    __shared__ float w[18];

    const int tid = threadIdx.x;
    if (tid < 18) w[tid] = exc_w[tid];
    if (tid == 511) out_dcmd[tb] = 0.f;              // zero-init dcmd (poisoned)

    for (int n = tid; n < 2 * 88; n += 512) {
        int c = n / 88, j = n % 88;
        p[c][0][j] = 0.f;  p[c][H_S + 1][j] = 0.f;
    }
    for (int n = tid; n < 2 * 67; n += 512) {
        int c = n / 67, i = n % 67;
        p[c][i][0] = 0.f;  p[c][i][W_S + 1] = 0.f;
    }
    __syncthreads();

    for (int n = tid; n < 2 * IMG; n += 512) {
        int c   = n / IMG;
        int rem = n - c * IMG;
        int i   = rem / W_S;
        int j   = rem - i * W_S;
        const float* src = xb + ((long long)c * HEIGHT + i * 4) * WIDTH + j * 4;
        float4 a  = *(const float4*)(src);
        float2 b0 = *(const float2*)(src + WIDTH);
        float2 b1 = *(const float2*)(src + WIDTH + 2);
        float4 c4 = *(const float4*)(src + 2 * WIDTH);
        float2 d0 = *(const float2*)(src + 3 * WIDTH);
        float2 d1 = *(const float2*)(src + 3 * WIDTH + 2);
        float s = a.x + a.y + a.z + a.w
                + b0.x + b0.y + b1.x + b1.y
                + c4.x + c4.y + c4.z + c4.w
                + d0.x + d0.y + d1.x + d1.y;
        p[c][i + 1][j + 1] = s * (1.f / 16.f);
    }
    __syncthreads();

    const bool t0 = (tb < BATCH);
    float* out  = g_exc  + (long long)tb * IMG;
    float* outl = g_lgmd + (long long)tb * IMG;
    for (int n = tid; n < IMG; n += 512) {
        int i = n / W_S;
        int j = n - i * W_S;
        float acc = 0.f;
        #pragma unroll
        for (int c = 0; c < 2; c++)
            #pragma unroll
            for (int ky = 0; ky < 3; ky++)
                #pragma unroll
                for (int kx = 0; kx < 3; kx++)
                    acc += p[c][i + ky][j + kx] * w[c * 9 + ky * 3 + kx];
        acc = fmaxf(acc, 0.f);
        out[n] = acc;
        if (t0) outl[n] = acc;                       // lgmd_in[0] = exc[0]
    }
}

// ---------------------------------------------------------------------------
// Kernel B: lgmd_in[t] = exc[t] - sepconv7x7(exc[t-1]), t >= 1.
// One block per (t,b) image; float2 staging / h-pass (5 LDS.64 -> 2 outputs)
// / v-pass. Symmetric Gaussian taps folded. Smem layout:
//   raw2[71][47]: ri = gc+4 (gc in [-4,89]), interior gc even -> f2 idx k+2
//   rp2 [71][44]: h-pass output pairs (c=2k, 2k+1)
// ---------------------------------------------------------------------------
#define IH   71                     // rows gr in [-3, 67]
#define W2   43

__global__ void __launch_bounds__(512)
k_inh(const float* __restrict__ inh_w) {
    const int tb  = blockIdx.x + BATCH;              // skip t=0
    const int tid = threadIdx.x;

    __shared__ float2 raw2[IH][47];
    __shared__ float2 rp2 [IH][44];

    float u[7];
    {
        float cnorm = rsqrtf(-__ldg(&inh_w[3 * 7 + 3]));
        #pragma unroll
        for (int j = 0; j < 7; j++) u[j] = -__ldg(&inh_w[3 * 7 + j]) * cnorm;
    }

    // zero halo (smem only — overlaps k_exc drain, before the PDL wait):
    // rows 0..2 and 68..70 full; cols f2 {0,1,45,46} for rows 3..67
    for (int n = tid; n < 6 * 47; n += 512) {
        int rr = n / 47, cc = n - rr * 47;
        int r = (rr < 3) ? rr : (65 + rr);
        raw2[r][cc] = make_float2(0.f, 0.f);
    }
    for (int n = tid; n < 65 * 4; n += 512) {
        int r = 3 + (n >> 2);
        int q = n & 3;
        int cc = (q < 2) ? q : (43 + q);             // 0,1,45,46
        raw2[r][cc] = make_float2(0.f, 0.f);
    }

#if defined(__CUDA_ARCH__) && (__CUDACC_VER_MAJOR__ >= 12)
    cudaGridDependencySynchronize();                 // g_exc ready beyond here
#endif

    // stage interior of exc[t-1]: 65 rows x 43 float2
    const float2* prev2 = (const float2*)(g_exc + (long long)(tb - BATCH) * IMG);
    for (int n = tid; n < 65 * W2; n += 512) {
        int r = n / W2;
        int k = n - r * W2;
        raw2[r + 3][k + 2] = __ldg(&prev2[n]);
    }
    __syncthreads();

    // horizontal 7-tap, 2 outputs/thread from 5 float2 LDS
    for (int n = tid; n < IH * W2; n += 512) {
        int r = n / W2;
        int k = n - r * W2;
        float2 q0 = raw2[r][k];
        float2 q1 = raw2[r][k + 1];
        float2 q2 = raw2[r][k + 2];
        float2 q3 = raw2[r][k + 3];
        float2 q4 = raw2[r][k + 4];
        // x_i = float at ri = 2k+i
        float a0 = u[0] * (q0.y + q3.y) + u[1] * (q1.x + q3.x)
                 + u[2] * (q1.y + q2.y) + u[3] * q2.x;
        float a1 = u[0] * (q1.x + q4.x) + u[1] * (q1.y + q3.y)
                 + u[2] * (q2.x + q3.x) + u[3] * q2.y;
        rp2[r][k] = make_float2(a0, a1);
    }
    __syncthreads();

    // vertical 7-tap + subtract from exc[t] -> g_lgmd, float2
    const float2* cur2 = (const float2*)(g_exc + (long long)tb * IMG);
    float2* out2 = (float2*)(g_lgmd + (long long)tb * IMG);
    for (int n = tid; n < H_S * W2; n += 512) {
        int r = n / W2;
        int c = n - r * W2;
        float2 r0 = rp2[r][c],     r1 = rp2[r + 1][c], r2 = rp2[r + 2][c];
        float2 r3 = rp2[r + 3][c], r4 = rp2[r + 4][c], r5 = rp2[r + 5][c];
        float2 r6 = rp2[r + 6][c];
        float cx = u[0] * (r0.x + r6.x) + u[1] * (r1.x + r5.x)
                 + u[2] * (r2.x + r4.x) + u[3] * r3.x;
        float cy = u[0] * (r0.y + r6.y) + u[1] * (r1.y + r5.y)
                 + u[2] * (r2.y + r4.y) + u[3] * r3.y;
        float2 ev = __ldg(&cur2[n]);
        ev.x -= cx;  ev.y -= cy;
        out2[n] = ev;
    }
    // no early trigger: g_lgmd must be fully written before k_scan's wait
    // releases (R10 had a latent race here).
}

// ---------------------------------------------------------------------------
// Kernel C: pointwise membrane scan + fused dcmd. 2 px/thread, depth-4
// prefetch ring, barrier-free, one RED per warp per step.
// ---------------------------------------------------------------------------
#define SCT   128
#define IMG2  (IMG / 2)                    // 2795
#define SCB   ((IMG2 + SCT - 1) / SCT)     // 22

__global__ void k_scan(const float* __restrict__ dcmd_w,
                       float* __restrict__ out_dcmd,
                       float* __restrict__ out_spk) {
    const int b   = blockIdx.y;
    const int tid = threadIdx.x;
    const int p2  = blockIdx.x * SCT + tid;
    const bool act = p2 < IMG2;

    const long long base2   = (long long)b * IMG2 + p2;
    const long long stride2 = (long long)BATCH * IMG2;
    const float2* lg2 = (const float2*)g_lgmd;
    float2* out2 = (float2*)out_spk;

    float a0 = 0.f, a1 = 0.f;
    if (act) {
        float2 wv = __ldg(&((const float2*)dcmd_w)[p2]);
        a0 = fabsf(wv.x);  a1 = fabsf(wv.y);
    }

#if defined(__CUDA_ARCH__) && (__CUDACC_VER_MAJOR__ >= 12)
    cudaGridDependencySynchronize();                 // g_lgmd ready beyond here
#endif

    float v0 = 0.f, v1 = 0.f;
    float2 ring[4];
    #pragma unroll
    for (int k = 0; k < 4; k++)
        ring[k] = act ? __ldg(&lg2[k * stride2 + base2]) : make_float2(0.f, 0.f);

    #pragma unroll 8
    for (int t = 0; t < T_STEPS; t++) {
        float2 lg = ring[t & 3];
        if (t + 4 < T_STEPS)
            ring[t & 3] = act ? __ldg(&lg2[(t + 4) * stride2 + base2])
                              : make_float2(0.f, 0.f);

        float vn0 = v0 + (lg.x - v0) * 0.5f;         // tau = 2 exact
        float vn1 = v1 + (lg.y - v1) * 0.5f;
        float sp0 = (vn0 >= 1.0f) ? 1.0f : 0.0f;
        float sp1 = (vn1 >= 1.0f) ? 1.0f : 0.0f;
        if (act) out2[t * stride2 + base2] = make_float2(sp0, sp1);
        v0 = vn0 * (1.0f - sp0);
        v1 = vn1 * (1.0f - sp1);

        float dsum = sp0 * a0 + sp1 * a1;
        #pragma unroll
        for (int off = 16; off; off >>= 1)
            dsum += __shfl_down_sync(0xffffffffu, dsum, off);
        if ((tid & 31) == 0 && dsum != 0.f)
            atomicAdd(&out_dcmd[t * BATCH + b], dsum);
    }
}

// helper: launch with PDL stream-serialization; plain launch on error
template <typename... Args>
static void launch_pdl(void (*kern)(Args...), dim3 grid, dim3 block,
                       cudaStream_t stream, Args... args) {
    cudaLaunchAttribute attr[1];
    attr[0].id = cudaLaunchAttributeProgrammaticStreamSerialization;
    attr[0].val.programmaticStreamSerializationAllowed = 1;
    cudaLaunchConfig_t cfg = {};
    cfg.gridDim = grid;  cfg.blockDim = block;
    cfg.dynamicSmemBytes = 0;  cfg.stream = stream;
    cfg.attrs = attr;  cfg.numAttrs = 1;
    cudaError_t err = cudaLaunchKernelEx(&cfg, kern, args...);
    if (err != cudaSuccess) {
        cudaGetLastError();
        kern<<<grid, block, 0, stream>>>(args...);
    }
}

extern "C" void kernel_launch(void* const* d_in, const int* in_sizes, int n_in,
                              void* d_out, int out_size) {
    const float* x      = (const float*)d_in[0];
    const float* exc_w  = (const float*)d_in[1];
    const float* inh_w  = (const float*)d_in[2];
    const float* dcmd_w = (const float*)d_in[3];

    float* out      = (float*)d_out;
    float* out_dcmd = out;                         // (T,B)
    float* out_spk  = out + T_STEPS * BATCH;       // (T,B,1,H_S,W_S)

    k_exc<<<T_STEPS * BATCH, 512>>>(x, exc_w, out_dcmd);

    launch_pdl(k_inh, dim3((T_STEPS - 1) * BATCH), dim3(512),
               (cudaStream_t)0, inh_w);

    launch_pdl(k_scan, dim3(SCB, BATCH), dim3(SCT),
               (cudaStream_t)0, dcmd_w, out_dcmd, out_spk);
}